// round 13
// baseline (speedup 1.0000x reference)
#include <cuda_runtime.h>
#include <cuda.h>
#include <cuda_fp16.h>
#include <dlfcn.h>
#include <math.h>
#include <stdint.h>

// ---------------- problem constants ----------------
#define T_DIM 1024
#define B_DIM 8
#define C_DIM 1024
#define F_DIM 4096
#define H_DIM 16
#define K_TAPS 15
#define M_DIM (T_DIM * B_DIM)   // 8192
#define NPAD 256
#define LN_EPS 1e-5f

#define KE 64                   // fp16 elements per k-chunk (128 bytes per row)

// dynconv tiling
#define TT 16
#define HALO (K_TAPS - 1)
#define XS_ROWS (TT + HALO)                          // 30
#define DC_XS_BYTES (XS_ROWS * C_DIM * 2)
#define DC_WS_OFF   DC_XS_BYTES
#define DC_WS_BYTES (TT * H_DIM * K_TAPS * 4)
#define DC_G_OFF    (DC_WS_OFF + DC_WS_BYTES)
#define DC_B_OFF    (DC_G_OFF + C_DIM * 4)
#define DC_SMEM     (DC_B_OFF + C_DIM * 4)

// arch-specific feature gate
#if defined(__CUDA_ARCH_FEAT_SM103_ALL) || defined(__CUDA_ARCH_FEAT_SM100_ALL) || \
    (defined(__CUDA_ARCH_SPECIFIC__) && (__CUDA_ARCH_SPECIFIC__ >= 1000)) ||      \
    (defined(__CUDA_ARCH_FAMILY_SPECIFIC__) && (__CUDA_ARCH_FAMILY_SPECIFIC__ >= 1000))
#define TC_OK 1
#else
#define TC_OK 0
#endif

// ---------------- scratch (device globals) ----------------
__device__ __half g_xh[(size_t)M_DIM * C_DIM];
__device__ __half g_wlinT[NPAD * C_DIM];
__device__ __half g_fc1wT[(size_t)F_DIM * C_DIM];
__device__ __half g_fc2wT[(size_t)C_DIM * F_DIM];
__device__ float  g_wraw[(size_t)M_DIM * NPAD];
__device__ float  g_y[(size_t)M_DIM * C_DIM];
__device__ __half g_yh[(size_t)M_DIM * C_DIM];
__device__ __half g_h[(size_t)M_DIM * F_DIM];

// ---------------- helpers ----------------
__device__ __forceinline__ uint32_t smem_u32(const void* p) {
    uint32_t a;
    asm("{ .reg .u64 t; cvta.to.shared.u64 t, %1; cvt.u32.u64 %0, t; }" : "=r"(a) : "l"(p));
    return a;
}
__device__ __forceinline__ uint32_t elect_one() {
    uint32_t p;
    asm volatile("{ .reg .pred p; elect.sync _|p, 0xFFFFFFFF; selp.b32 %0, 1, 0, p; }" : "=r"(p));
    return p;
}
__device__ __forceinline__ void mbar_init(uint32_t a, uint32_t cnt) {
    asm volatile("mbarrier.init.shared.b64 [%0], %1;" :: "r"(a), "r"(cnt) : "memory");
}
__device__ __forceinline__ void mbar_expect_tx(uint32_t a, uint32_t bytes) {
    asm volatile("mbarrier.arrive.expect_tx.shared.b64 _, [%0], %1;" :: "r"(a), "r"(bytes) : "memory");
}
__device__ __forceinline__ void mbar_wait(uint32_t a, uint32_t parity) {
    uint32_t done;
    asm volatile(
        "{ .reg .pred p;\n\t"
        "mbarrier.try_wait.parity.acquire.cta.shared::cta.b64 p, [%1], %2;\n\t"
        "selp.b32 %0, 1, 0, p; }" : "=r"(done) : "r"(a), "r"(parity) : "memory");
    if (!done) {
        asm volatile(
            "{ .reg .pred P1;\n\t"
            "WL_%=:\n\t"
            "mbarrier.try_wait.parity.acquire.cta.shared::cta.b64 P1, [%0], %1, 0x989680;\n\t"
            "@P1 bra.uni WD_%=;\n\t"
            "bra.uni WL_%=;\n\t"
            "WD_%=: }" :: "r"(a), "r"(parity) : "memory");
    }
}
#if TC_OK
__device__ __forceinline__ uint32_t cluster_rank() {
    uint32_t r;
    asm("mov.u32 %0, %%cluster_ctarank;" : "=r"(r));
    return r;
}
__device__ __forceinline__ void mbar_arrive_cluster(uint32_t local_addr, uint32_t target_rank) {
    asm volatile(
        "{ .reg .b32 ra;\n\t"
        "mapa.shared::cluster.u32 ra, %0, %1;\n\t"
        "mbarrier.arrive.shared::cluster.b64 _, [ra]; }"
        :: "r"(local_addr), "r"(target_rank) : "memory");
}
#define CLUSTER_SYNC() do { \
    asm volatile("barrier.cluster.arrive.aligned;" ::: "memory"); \
    asm volatile("barrier.cluster.wait.aligned;" ::: "memory");   \
} while (0)

__device__ __forceinline__ void tma_2d(uint32_t dst, const void* map, int cx, int cy, uint32_t mbar) {
    asm volatile(
        "cp.async.bulk.tensor.2d.shared::cta.global.tile.mbarrier::complete_tx::bytes "
        "[%0], [%1, {%2, %3}], [%4];"
        :: "r"(dst), "l"(map), "r"(cx), "r"(cy), "r"(mbar) : "memory");
}
__device__ __forceinline__ void tma_3d_cg2(uint32_t dst, const void* map, int cx, int cy,
                                           uint32_t mbar) {
    asm volatile(
        "{\n\t"
        ".reg .b32 leaderBar;\n\t"
        "and.b32 leaderBar, %4, 0xFEFFFFFF;\n\t"
        "cp.async.bulk.tensor.3d.cta_group::2.shared::cluster.global"
        ".tile.mbarrier::complete_tx::bytes "
        "[%0], [%1, {%2, %3, %5}], [leaderBar];\n\t"
        "}"
        :: "r"(dst), "l"(map), "r"(cx), "r"(cy), "r"(mbar), "r"(0) : "memory");
}
__device__ __forceinline__ void mma_f16_ss(uint32_t d, uint64_t adesc, uint64_t bdesc,
                                           uint32_t idesc, uint32_t en) {
    asm volatile(
        "{ .reg .pred p;\n\t"
        "setp.ne.u32 p, %4, 0;\n\t"
        "tcgen05.mma.cta_group::1.kind::f16 [%0], %1, %2, %3, p; }"
        :: "r"(d), "l"(adesc), "l"(bdesc), "r"(idesc), "r"(en) : "memory");
}
__device__ __forceinline__ void mma_f16_ss_cg2(uint32_t d, uint64_t adesc, uint64_t bdesc,
                                               uint32_t idesc, uint32_t en) {
    asm volatile(
        "{ .reg .pred p;\n\t"
        "setp.ne.u32 p, %5, 0;\n\t"
        "tcgen05.mma.cta_group::2.kind::f16 [%0], %1, %2, %3, "
        "{%4, %4, %4, %4, %4, %4, %4, %4}, p; }"
        :: "r"(d), "l"(adesc), "l"(bdesc), "r"(idesc), "r"(0u), "r"(en) : "memory");
}
__device__ __forceinline__ void tc_commit(uint32_t mbar) {
    asm volatile(
        "tcgen05.commit.cta_group::1.mbarrier::arrive::one.shared::cluster.b64 [%0];"
        :: "r"(mbar) : "memory");
}
__device__ __forceinline__ void tc_commit_mc_cg2(uint32_t mbar, uint16_t mask) {
    asm volatile(
        "tcgen05.commit.cta_group::2.mbarrier::arrive::one.shared::cluster.multicast::cluster.b64 "
        "[%0], %1;"
        :: "r"(mbar), "h"(mask) : "memory");
}
#define TC_ALLOC(smem_addr, ncols) \
    asm volatile("tcgen05.alloc.cta_group::1.sync.aligned.shared::cta.b32 [%0], %1;" \
                 :: "r"(smem_addr), "r"(ncols) : "memory")
#define TC_RELINQ() \
    asm volatile("tcgen05.relinquish_alloc_permit.cta_group::1.sync.aligned;")
#define TC_DEALLOC(tmem, ncols) \
    asm volatile("tcgen05.dealloc.cta_group::1.sync.aligned.b32 %0, %1;" :: "r"(tmem), "r"(ncols))
#define TC_ALLOC_CG2(smem_addr, ncols) \
    asm volatile("tcgen05.alloc.cta_group::2.sync.aligned.shared::cta.b32 [%0], %1;" \
                 :: "r"(smem_addr), "r"(ncols) : "memory")
#define TC_RELINQ_CG2() \
    asm volatile("tcgen05.relinquish_alloc_permit.cta_group::2.sync.aligned;")
#define TC_DEALLOC_CG2(tmem, ncols) \
    asm volatile("tcgen05.dealloc.cta_group::2.sync.aligned.b32 %0, %1;" :: "r"(tmem), "r"(ncols))
#define TC_FENCE_AFTER()  asm volatile("tcgen05.fence::after_thread_sync;" ::: "memory")
#define TC_WAIT_LD()      asm volatile("tcgen05.wait::ld.sync.aligned;" ::: "memory")
#define TC_LD_X32(r, addr) \
    asm volatile("tcgen05.ld.sync.aligned.32x32b.x32.b32 " \
        "{%0, %1, %2, %3, %4, %5, %6, %7, %8, %9, %10, %11, %12, %13, %14, %15, " \
        " %16, %17, %18, %19, %20, %21, %22, %23, %24, %25, %26, %27, %28, %29, %30, %31}, [%32];" \
        : "=r"((r)[0]), "=r"((r)[1]), "=r"((r)[2]), "=r"((r)[3]), \
          "=r"((r)[4]), "=r"((r)[5]), "=r"((r)[6]), "=r"((r)[7]), \
          "=r"((r)[8]), "=r"((r)[9]), "=r"((r)[10]), "=r"((r)[11]), \
          "=r"((r)[12]), "=r"((r)[13]), "=r"((r)[14]), "=r"((r)[15]), \
          "=r"((r)[16]), "=r"((r)[17]), "=r"((r)[18]), "=r"((r)[19]), \
          "=r"((r)[20]), "=r"((r)[21]), "=r"((r)[22]), "=r"((r)[23]), \
          "=r"((r)[24]), "=r"((r)[25]), "=r"((r)[26]), "=r"((r)[27]), \
          "=r"((r)[28]), "=r"((r)[29]), "=r"((r)[30]), "=r"((r)[31]) \
        : "r"(addr))

__device__ __forceinline__ uint64_t smem_desc_sw128(uint32_t addr) {
    return ((uint64_t)2 << 61) | ((uint64_t)1 << 46) | ((uint64_t)64 << 32) |
           ((uint64_t)1 << 16) | (((uint64_t)addr >> 4) & 0x3FFF);
}
__device__ __forceinline__ constexpr uint32_t idesc_f16(int bn, int m) {
    return (1u << 4) | ((uint32_t)(bn / 8) << 17) | ((uint32_t)(m / 16) << 24);
}
#endif  // TC_OK

#if TC_OK
template <int EPI>
__device__ __forceinline__ void epi_write_chunk(const uint32_t* r, int row, int colbase,
                                                const float* __restrict__ bias,
                                                const float* __restrict__ res,
                                                void* __restrict__ Cv, int N) {
    if (EPI == 1) {
        __half* Ch = (__half*)Cv;
        __half2* dst = reinterpret_cast<__half2*>(&Ch[(size_t)row * N + colbase]);
        #pragma unroll
        for (int j = 0; j < 32; j += 2) {
            float v0 = fmaxf(__uint_as_float(r[j + 0]) + bias[colbase + j + 0], 0.f);
            float v1 = fmaxf(__uint_as_float(r[j + 1]) + bias[colbase + j + 1], 0.f);
            dst[j / 2] = __floats2half2_rn(v0, v1);
        }
    } else {
        float* C = (float*)Cv;
        float4* dst = reinterpret_cast<float4*>(&C[(size_t)row * N + colbase]);
        #pragma unroll
        for (int j = 0; j < 32; j += 4) {
            float4 v;
            v.x = __uint_as_float(r[j + 0]);
            v.y = __uint_as_float(r[j + 1]);
            v.z = __uint_as_float(r[j + 2]);
            v.w = __uint_as_float(r[j + 3]);
            if (EPI == 2) {
                v.x += bias[colbase + j + 0]; v.y += bias[colbase + j + 1];
                v.z += bias[colbase + j + 2]; v.w += bias[colbase + j + 3];
                float4 rv = *reinterpret_cast<const float4*>(&res[(size_t)row * N + colbase + j]);
                v.x += rv.x; v.y += rv.y; v.z += rv.z; v.w += rv.w;
            }
            dst[j / 4] = v;
        }
    }
}
#endif

// ================= plain warp-specialized tcgen05 fp16 GEMM (GEMM1) =================
template <int EPI, int BN_, int STG>
__global__ __launch_bounds__(256)
void tc_gemm_plain(const __grid_constant__ CUtensorMap tmA,
                   const __grid_constant__ CUtensorMap tmB,
                   const float* __restrict__ bias, const float* __restrict__ res,
                   void* __restrict__ C, int N, int NC) {
#if TC_OK
    constexpr int CA = 128 * 128;
    constexpr int CB = BN_ * 128;
    constexpr int CBYTES = CA + CB;
    constexpr int TCOLS = BN_;

    extern __shared__ __align__(1024) char smem[];
    const int tid  = threadIdx.x;
    const int warp = tid >> 5;
    const int lane = tid & 31;

    uint32_t sb = (smem_u32(smem) + 1023u) & ~1023u;
    const uint32_t tmem_ptr_addr = sb;
    const uint32_t mb_all = sb + 8 + 16 * STG;
    uint32_t mb_full[STG], mb_done[STG], bufA[STG], bufB[STG];
    #pragma unroll
    for (int s = 0; s < STG; s++) {
        mb_full[s] = sb + 8 + 8 * s;
        mb_done[s] = sb + 8 + 8 * STG + 8 * s;
        bufA[s] = sb + 1024 + s * CBYTES;
        bufB[s] = bufA[s] + CA;
    }

    if (warp == 0) { TC_ALLOC(tmem_ptr_addr, TCOLS); TC_RELINQ(); }
    if (tid == 0) {
        #pragma unroll
        for (int s = 0; s < STG; s++) { mbar_init(mb_full[s], 1); mbar_init(mb_done[s], 1); }
        mbar_init(mb_all, 1);
    }
    __syncthreads();

    uint32_t tmem;
    asm volatile("ld.shared.b32 %0, [%1];" : "=r"(tmem) : "r"(tmem_ptr_addr));

    const int tile_m = blockIdx.y * 128;
    const int tile_n = blockIdx.x * BN_;

    if (warp == 1 && elect_one()) {
        uint32_t phd = 0;
        for (int j = 0; j < NC; j++) {
            const int s = j % STG;
            if (j >= STG) { mbar_wait(mb_done[s], (phd >> s) & 1); phd ^= 1u << s; }
            mbar_expect_tx(mb_full[s], CBYTES);
            tma_2d(bufA[s], &tmA, j * KE, tile_m, mb_full[s]);
            tma_2d(bufB[s], &tmB, j * KE, tile_n, mb_full[s]);
        }
    }
    if (warp == 0 && elect_one()) {
        uint64_t ad[STG], bd[STG];
        #pragma unroll
        for (int s = 0; s < STG; s++) {
            ad[s] = smem_desc_sw128(bufA[s]);
            bd[s] = smem_desc_sw128(bufB[s]);
        }
        uint32_t phf = 0;
        for (int kc = 0; kc < NC; kc++) {
            const int s = kc % STG;
            mbar_wait(mb_full[s], (phf >> s) & 1); phf ^= 1u << s;
            #pragma unroll
            for (int s2 = 0; s2 < 4; s2++) {
                const uint32_t en = (kc > 0 || s2 > 0) ? 1u : 0u;
                mma_f16_ss(tmem, ad[s] + 2 * s2, bd[s] + 2 * s2, idesc_f16(BN_, 128), en);
            }
            tc_commit(mb_done[s]);
        }
        tc_commit(mb_all);
        mbar_wait(mb_all, 0);
    }
    __syncthreads();
    TC_FENCE_AFTER();
    {
        const int half_ = warp >> 2;
        const uint32_t dbase = tmem + half_ * (BN_ / 2);
        const int row = tile_m + (warp & 3) * 32 + lane;
        const int col0 = tile_n + half_ * (BN_ / 2);
        #pragma unroll 1
        for (int cc = 0; cc < BN_ / 64; cc++) {
            uint32_t r[32];
            TC_LD_X32(r, dbase + cc * 32);
            TC_WAIT_LD();
            epi_write_chunk<EPI>(r, row, col0 + cc * 32, bias, res, C, N);
        }
    }
    __syncthreads();
    if (warp == 0) TC_DEALLOC(tmem, TCOLS);
#endif
}

// ========== persistent cg2 pair GEMM: 512x256 tiles, 74 pairs loop over all tiles ==========
// 320 threads: warps 0-7 epilogue, warp 8 producer, warp 9 consumer (leader only).
// Ring stays warm across tiles; epilogue overlaps the next tile's TMA fill.
template <int EPI>
__global__ __launch_bounds__(320) __cluster_dims__(2, 1, 1)
void tc_gemm_cg2p(const __grid_constant__ CUtensorMap tmA,
                  const __grid_constant__ CUtensorMap tmB,
                  const float* __restrict__ bias, const float* __restrict__ res,
                  void* __restrict__ C, int N, int NC, int ntiles, int ntilesN) {
#if TC_OK
    constexpr int STG = 4;
    constexpr int CA = 2 * 128 * 128;          // 32 KB (two A row-blocks)
    constexpr int CB = 128 * 128;              // 16 KB
    constexpr int CBYTES = CA + CB;            // 48 KB per CTA per stage
    constexpr int PAIR_BYTES = 2 * CBYTES;     // 96 KB
    constexpr int TCOLS = 512;

    extern __shared__ __align__(1024) char smem[];
    const int tid  = threadIdx.x;
    const int warp = tid >> 5;
    const int lane = tid & 31;

    uint32_t sb = (smem_u32(smem) + 1023u) & ~1023u;
    const uint32_t tmem_ptr_addr = sb;
    uint32_t mb_full[STG], mb_done[STG], bufA[STG], bufB[STG];
    #pragma unroll
    for (int s = 0; s < STG; s++) {
        mb_full[s] = sb + 8 + 8 * s;
        mb_done[s] = sb + 8 + 8 * STG + 8 * s;
        bufA[s] = sb + 1024 + s * CBYTES;
        bufB[s] = bufA[s] + CA;
    }
    const uint32_t mb_tdone = sb + 8 + 16 * STG;       // tile_done (multicast target)
    const uint32_t mb_efree = sb + 16 + 16 * STG;      // epi_free (leader only; count 2)

    if (warp == 0) { TC_ALLOC_CG2(tmem_ptr_addr, TCOLS); TC_RELINQ_CG2(); }
    if (tid == 0) {
        #pragma unroll
        for (int s = 0; s < STG; s++) { mbar_init(mb_full[s], 1); mbar_init(mb_done[s], 1); }
        mbar_init(mb_tdone, 1);
        mbar_init(mb_efree, 2);
    }
    __syncthreads();
    CLUSTER_SYNC();

    uint32_t tmem;
    asm volatile("ld.shared.b32 %0, [%1];" : "=r"(tmem) : "r"(tmem_ptr_addr));

    const int rank   = (int)cluster_rank();
    const int pair   = (int)(blockIdx.x >> 1);
    const int npairs = (int)(gridDim.x >> 1);

    // ---------------- producer (warp 8, both CTAs) ----------------
    if (warp == 8 && elect_one()) {
        uint32_t phd = 0;
        int gchunk = 0;
        for (int t = pair; t < ntiles; t += npairs) {
            const int tile_m = (t / ntilesN) * 512;
            const int tile_n = (t % ntilesN) * 256;
            const int rowA0 = tile_m + rank * 128;
            const int rowA1 = tile_m + 256 + rank * 128;
            const int rowB  = tile_n + rank * 128;
            for (int j = 0; j < NC; j++) {
                const int s = gchunk & (STG - 1);
                if (gchunk >= STG) { mbar_wait(mb_done[s], (phd >> s) & 1); phd ^= 1u << s; }
                if (rank == 0) mbar_expect_tx(mb_full[s], PAIR_BYTES);
                tma_3d_cg2(bufA[s],         &tmA, j * KE, rowA0, mb_full[s]);
                tma_3d_cg2(bufA[s] + 16384, &tmA, j * KE, rowA1, mb_full[s]);
                tma_3d_cg2(bufB[s],         &tmB, j * KE, rowB,  mb_full[s]);
                gchunk++;
            }
        }
    }
    // ---------------- consumer (warp 9, leader only) ----------------
    if (rank == 0 && warp == 9 && elect_one()) {
        uint64_t adLo[STG], adHi[STG], bd[STG];
        #pragma unroll
        for (int s = 0; s < STG; s++) {
            adLo[s] = smem_desc_sw128(bufA[s]);
            adHi[s] = smem_desc_sw128(bufA[s] + 16384);
            bd[s]   = smem_desc_sw128(bufB[s]);
        }
        uint32_t phf = 0;
        int gchunk = 0, tilecnt = 0;
        for (int t = pair; t < ntiles; t += npairs) {
            if (tilecnt > 0) {                        // wait until epilogue released TMEM
                mbar_wait(mb_efree, (tilecnt - 1) & 1);
                TC_FENCE_AFTER();
            }
            for (int j = 0; j < NC; j++) {
                const int s = gchunk & (STG - 1);
                mbar_wait(mb_full[s], (phf >> s) & 1); phf ^= 1u << s;
                #pragma unroll
                for (int s2 = 0; s2 < 4; s2++) {
                    const uint32_t en = (j > 0 || s2 > 0) ? 1u : 0u;
                    mma_f16_ss_cg2(tmem,       adLo[s] + 2 * s2, bd[s] + 2 * s2,
                                   idesc_f16(256, 256), en);
                    mma_f16_ss_cg2(tmem + 256, adHi[s] + 2 * s2, bd[s] + 2 * s2,
                                   idesc_f16(256, 256), en);
                }
                tc_commit_mc_cg2(mb_done[s], 0x3);
                gchunk++;
            }
            tc_commit_mc_cg2(mb_tdone, 0x3);          // tile complete -> both CTAs
            tilecnt++;
        }
    }
    // ---------------- epilogue (warps 0-7, both CTAs) ----------------
    if (warp < 8) {
        int tilecnt = 0;
        for (int t = pair; t < ntiles; t += npairs) {
            const int tile_m = (t / ntilesN) * 512;
            const int tile_n = (t % ntilesN) * 256;
            mbar_wait(mb_tdone, tilecnt & 1);
            TC_FENCE_AFTER();
            const int half_ = warp >> 2;
            const uint32_t dbase = tmem + half_ * 256;
            const int row = tile_m + half_ * 256 + rank * 128 + (warp & 3) * 32 + lane;
            #pragma unroll 1
            for (int cc = 0; cc < 8; cc++) {
                uint32_t r[32];
                TC_LD_X32(r, dbase + cc * 32);
                TC_WAIT_LD();
                epi_write_chunk<EPI>(r, row, tile_n + cc * 32, bias, res, C, N);
            }
            asm volatile("bar.sync 10, 256;" ::: "memory");   // epi warps of this CTA
            if (tid == 0) mbar_arrive_cluster(mb_efree, 0);   // release TMEM to consumer
            tilecnt++;
        }
    }
    __syncthreads();
    if (warp == 0) TC_DEALLOC_CG2(tmem, TCOLS);
    CLUSTER_SYNC();
#endif
}

// ================= fused prep: x->fp16 + all three fp16 transposes =================
#define F2H_BLOCKS 16384
#define TW_BLOCKS  128
#define T1_BLOCKS  2048
#define T2_BLOCKS  2048
#define PREP_BLOCKS (F2H_BLOCKS + TW_BLOCKS + T1_BLOCKS + T2_BLOCKS)

__global__ void prep_kernel(const float* __restrict__ x, __half* __restrict__ xh,
                            const float* __restrict__ w_lin, __half* __restrict__ wlinT,
                            const float* __restrict__ fc1_w, __half* __restrict__ fc1wT,
                            const float* __restrict__ fc2_w, __half* __restrict__ fc2wT) {
    __shared__ float tile[64][33];
    const int tx = threadIdx.x, ty = threadIdx.y;
    int bid = blockIdx.x;

    if (bid < F2H_BLOCKS) {
        const int i = bid * 256 + ty * 32 + tx;
        float2 v = reinterpret_cast<const float2*>(x)[i];
        reinterpret_cast<__half2*>(xh)[i] = __floats2half2_rn(v.x, v.y);
        return;
    }
    bid -= F2H_BLOCKS;

    const float* in; __half* out;
    int R, Cc, Cp, gx;
    if (bid < TW_BLOCKS) {
        in = w_lin; out = wlinT; R = C_DIM; Cc = H_DIM * K_TAPS; Cp = NPAD; gx = NPAD / 32;
    } else if (bid < TW_BLOCKS + T1_BLOCKS) {
        bid -= TW_BLOCKS;
        in = fc1_w; out = fc1wT; R = C_DIM; Cc = F_DIM; Cp = F_DIM; gx = F_DIM / 32;
    } else {
        bid -= TW_BLOCKS + T1_BLOCKS;
        in = fc2_w; out = fc2wT; R = F_DIM; Cc = C_DIM; Cp = C_DIM; gx = C_DIM / 32;
    }
    const int c0 = (bid % gx) * 32;
    const int r0 = (bid / gx) * 64;

    #pragma unroll
    for (int i = 0; i < 64; i += 8) {
        const int y = r0 + ty + i;
        const int xq = c0 + tx;
        float v = 0.f;
        if (xq < Cc && y < R) v = in[(size_t)y * Cc + xq];
        tile[ty + i][tx] = v;
    }
    __syncthreads();
    #pragma unroll
    for (int i = 0; i < 32; i += 8) {
        const int oy = c0 + ty + i;
        const int ox = r0 + 2 * tx;
        if (oy < Cp) {
            __half2 v = __floats2half2_rn(tile[2 * tx][ty + i], tile[2 * tx + 1][ty + i]);
            *reinterpret_cast<__half2*>(&out[(size_t)oy * R + ox]) = v;
        }
    }
}

// ================= warp-per-timestep softmax + causal conv + LayerNorm =================
__global__ __launch_bounds__(512, 2)
void dynconv_ln_kernel(const __half* __restrict__ xh, const float* __restrict__ wraw,
                       const float* __restrict__ b_lin,
                       const float* __restrict__ ln_g, const float* __restrict__ ln_b,
                       float* __restrict__ y, __half* __restrict__ yh) {
    extern __shared__ char smc[];
    __half2* xs2 = reinterpret_cast<__half2*>(smc);
    float*   ws  = reinterpret_cast<float*>(smc + DC_WS_OFF);
    float*   g_s = reinterpret_cast<float*>(smc + DC_G_OFF);
    float*   b_s = reinterpret_cast<float*>(smc + DC_B_OFF);

    const int t0  = blockIdx.x * TT;
    const int b   = blockIdx.y;
    const int tid = threadIdx.x;

    {
        uint4* dst = reinterpret_cast<uint4*>(smc);
        const int total = XS_ROWS * (C_DIM / 8);
        for (int i = tid; i < total; i += 512) {
            const int r = i / (C_DIM / 8);
            const int cc = i % (C_DIM / 8);
            const int t = t0 - HALO + r;
            uint4 v = make_uint4(0u, 0u, 0u, 0u);
            if (t >= 0)
                v = reinterpret_cast<const uint4*>(&xh[((size_t)(t * B_DIM + b)) * C_DIM])[cc];
            dst[i] = v;
        }
    }
    for (int i = tid; i < TT * (H_DIM * K_TAPS); i += 512) {
        const int lt = i / (H_DIM * K_TAPS);
        const int j  = i % (H_DIM * K_TAPS);
        ws[i] = wraw[(size_t)((t0 + lt) * B_DIM + b) * NPAD + j] + b_lin[j];
    }
    for (int i = tid; i < C_DIM; i += 512) { g_s[i] = ln_g[i]; b_s[i] = ln_b[i]; }
    __syncthreads();

    if (tid < TT * H_DIM) {
        const int lt = tid >> 4;
        const int hd = tid & 15;
        float* p = ws + lt * (H_DIM * K_TAPS) + hd * K_TAPS;
        float mx = -1e30f;
        #pragma unroll
        for (int k = 0; k < K_TAPS; k++) mx = fmaxf(mx, p[k]);
        float e[K_TAPS]; float s = 0.f;
        #pragma unroll
        for (int k = 0; k < K_TAPS; k++) { e[k] = expf(p[k] - mx); s += e[k]; }
        const float inv = 1.0f / s;
        #pragma unroll
        for (int k = 0; k < K_TAPS; k++) p[k] = e[k] * inv;
    }
    __syncthreads();

    const int w    = tid >> 5;
    const int lane = tid & 31;
    const float* wrow = ws + w * (H_DIM * K_TAPS);

    __half2 ah[16];
    float s1 = 0.f, s2 = 0.f;
    #pragma unroll
    for (int j = 0; j < 16; j++) {
        float acc0 = 0.f, acc1 = 0.f;
        #pragma unroll
        for (int k = 0; k < K_TAPS; k++) {
            const float wgt = wrow[j * K_TAPS + k];
            const float2 xv = __half22float2(xs2[(w + k) * (C_DIM / 2) + lane + 32 * j]);
            acc0 += wgt * xv.x;
            acc1 += wgt * xv.y;
        }
        ah[j] = __floats2half2_rn(acc0, acc1);
        s1 += acc0 + acc1;
        s2 += acc0 * acc0 + acc1 * acc1;
    }
    #pragma unroll
    for (int off = 16; off > 0; off >>= 1) {
        s1 += __shfl_xor_sync(0xFFFFFFFFu, s1, off);
        s2 += __shfl_xor_sync(0xFFFFFFFFu, s2, off);
    }
    const float mu   = s1 * (1.0f / C_DIM);
    const float var  = s2 * (1.0f / C_DIM) - mu * mu;
    const float rstd = rsqrtf(var + LN_EPS);

    const size_t base = (size_t)((t0 + w) * B_DIM + b) * C_DIM;
    #pragma unroll
    for (int j = 0; j < 16; j++) {
        const int c = 2 * lane + 64 * j;
        const float2 a = __half22float2(ah[j]);
        const float v0 = (a.x - mu) * rstd * g_s[c]     + b_s[c];
        const float v1 = (a.y - mu) * rstd * g_s[c + 1] + b_s[c + 1];
        *reinterpret_cast<float2*>(&y[base + c])   = make_float2(v0, v1);
        *reinterpret_cast<__half2*>(&yh[base + c]) = __floats2half2_rn(v0, v1);
    }
}

// ================= host side =================
typedef CUresult (*PFN_encodeTiled)(CUtensorMap*, CUtensorMapDataType, cuuint32_t, void*,
                                    const cuuint64_t*, const cuuint64_t*, const cuuint32_t*,
                                    const cuuint32_t*, CUtensorMapInterleave, CUtensorMapSwizzle,
                                    CUtensorMapL2promotion, CUtensorMapFloatOOBfill);

static PFN_encodeTiled get_encoder() {
    static PFN_encodeTiled fn = nullptr;
    if (!fn) {
        void* h = dlopen("libcuda.so.1", RTLD_LAZY | RTLD_GLOBAL);
        if (!h) h = dlopen("libcuda.so", RTLD_LAZY | RTLD_GLOBAL);
        if (h) fn = (PFN_encodeTiled)dlsym(h, "cuTensorMapEncodeTiled");
    }
    return fn;
}

static void make_map_h2(CUtensorMap* m, const void* ptr, uint64_t d0, uint64_t d1, uint32_t b1) {
    cuuint64_t dims[2] = { d0, d1 };
    cuuint64_t strides[1] = { d0 * 2 };
    cuuint32_t box[2] = { KE, b1 };
    cuuint32_t es[2] = { 1, 1 };
    PFN_encodeTiled enc = get_encoder();
    if (enc)
        enc(m, CU_TENSOR_MAP_DATA_TYPE_FLOAT16, 2, (void*)ptr, dims, strides, box, es,
            CU_TENSOR_MAP_INTERLEAVE_NONE, CU_TENSOR_MAP_SWIZZLE_128B,
            CU_TENSOR_MAP_L2_PROMOTION_L2_128B, CU_TENSOR_MAP_FLOAT_OOB_FILL_NONE);
}
static void make_map_h3(CUtensorMap* m, const void* ptr, uint64_t d0, uint64_t d1) {
    cuuint64_t dims[3] = { d0, d1, 1 };
    cuuint64_t strides[2] = { d0 * 2, d0 * d1 * 2 };
    cuuint32_t box[3] = { KE, 128, 1 };
    cuuint32_t es[3] = { 1, 1, 1 };
    PFN_encodeTiled enc = get_encoder();
    if (enc)
        enc(m, CU_TENSOR_MAP_DATA_TYPE_FLOAT16, 3, (void*)ptr, dims, strides, box, es,
            CU_TENSOR_MAP_INTERLEAVE_NONE, CU_TENSOR_MAP_SWIZZLE_128B,
            CU_TENSOR_MAP_L2_PROMOTION_L2_128B, CU_TENSOR_MAP_FLOAT_OOB_FILL_NONE);
}

extern "C" void kernel_launch(void* const* d_in, const int* in_sizes, int n_in,
                              void* d_out, int out_size) {
    const float* x     = (const float*)d_in[0];
    const float* w_lin = (const float*)d_in[1];
    const float* b_lin = (const float*)d_in[2];
    const float* ln_g  = (const float*)d_in[3];
    const float* ln_b  = (const float*)d_in[4];
    const float* fc1_w = (const float*)d_in[5];
    const float* fc1_b = (const float*)d_in[6];
    const float* fc2_w = (const float*)d_in[7];
    const float* fc2_b = (const float*)d_in[8];
    float* out = (float*)d_out;

    __half *xh, *wlinT, *fc1wT, *fc2wT, *yh, *h;
    float *wraw, *y;
    cudaGetSymbolAddress((void**)&xh, g_xh);
    cudaGetSymbolAddress((void**)&wlinT, g_wlinT);
    cudaGetSymbolAddress((void**)&fc1wT, g_fc1wT);
    cudaGetSymbolAddress((void**)&fc2wT, g_fc2wT);
    cudaGetSymbolAddress((void**)&wraw, g_wraw);
    cudaGetSymbolAddress((void**)&y, g_y);
    cudaGetSymbolAddress((void**)&yh, g_yh);
    cudaGetSymbolAddress((void**)&h, g_h);

    const int smem_g1  = 1024 + 5 * (128 * 128 + 128 * 128);
    const int smem_cg2 = 1024 + 4 * (2 * 128 * 128 + 128 * 128);
    cudaFuncSetAttribute((const void*)tc_gemm_plain<0, 128, 5>,
                         cudaFuncAttributeMaxDynamicSharedMemorySize, smem_g1);
    cudaFuncSetAttribute((const void*)tc_gemm_cg2p<1>,
                         cudaFuncAttributeMaxDynamicSharedMemorySize, smem_cg2);
    cudaFuncSetAttribute((const void*)tc_gemm_cg2p<2>,
                         cudaFuncAttributeMaxDynamicSharedMemorySize, smem_cg2);
    cudaFuncSetAttribute((const void*)dynconv_ln_kernel,
                         cudaFuncAttributeMaxDynamicSharedMemorySize, DC_SMEM);

    CUtensorMap mA1{}, mB1{}, mA2{}, mB2{}, mA3{}, mB3{};
    make_map_h2(&mA1, xh,    C_DIM, M_DIM, 128);
    make_map_h2(&mB1, wlinT, C_DIM, NPAD,  128);
    make_map_h3(&mA2, yh,    C_DIM, M_DIM);
    make_map_h3(&mB2, fc1wT, C_DIM, F_DIM);
    make_map_h3(&mA3, h,     F_DIM, M_DIM);
    make_map_h3(&mB3, fc2wT, F_DIM, C_DIM);

    // 1) fused prep
    prep_kernel<<<PREP_BLOCKS, dim3(32, 8)>>>(x, xh, w_lin, wlinT, fc1_w, fc1wT, fc2_w, fc2wT);
    // 2) conv-weight projection
    tc_gemm_plain<0, 128, 5><<<dim3(NPAD / 128, M_DIM / 128), 256, smem_g1>>>(
        mA1, mB1, nullptr, nullptr, wraw, NPAD, C_DIM / KE);
    // 3) softmax + conv + LN
    dynconv_ln_kernel<<<dim3(T_DIM / TT, B_DIM), 512, DC_SMEM>>>(
        xh, wraw, b_lin, ln_g, ln_b, y, yh);
    // 4) fc1 + ReLU -> fp16 h : persistent, 148 CTAs, 256 tiles (16m x 16n)
    tc_gemm_cg2p<1><<<148, 320, smem_cg2>>>(
        mA2, mB2, fc1_b, nullptr, h, F_DIM, C_DIM / KE, 256, 16);
    // 5) fc2 + bias + residual -> fp32 out : persistent, 64 tiles (16m x 4n)
    tc_gemm_cg2p<2><<<148, 320, smem_cg2>>>(
        mA3, mB3, fc2_b, y, out, C_DIM, F_DIM / KE, 64, 4);
}

// round 14
// speedup vs baseline: 1.1117x; 1.1117x over previous
#include <cuda_runtime.h>
#include <cuda.h>
#include <cuda_fp16.h>
#include <dlfcn.h>
#include <math.h>
#include <stdint.h>

// ---------------- problem constants ----------------
#define T_DIM 1024
#define B_DIM 8
#define C_DIM 1024
#define F_DIM 4096
#define H_DIM 16
#define K_TAPS 15
#define M_DIM (T_DIM * B_DIM)   // 8192
#define NPAD 256
#define LN_EPS 1e-5f

#define KE 64                   // fp16 elements per k-chunk (128 bytes per row)

// dynconv tiling
#define TT 16
#define HALO (K_TAPS - 1)
#define XS_ROWS (TT + HALO)
#define DC_XS_BYTES (XS_ROWS * C_DIM * 2)
#define DC_WS_OFF   DC_XS_BYTES
#define DC_WS_BYTES (TT * H_DIM * K_TAPS * 4)
#define DC_G_OFF    (DC_WS_OFF + DC_WS_BYTES)
#define DC_B_OFF    (DC_G_OFF + C_DIM * 4)
#define DC_SMEM     (DC_B_OFF + C_DIM * 4)

// arch-specific feature gate
#if defined(__CUDA_ARCH_FEAT_SM103_ALL) || defined(__CUDA_ARCH_FEAT_SM100_ALL) || \
    (defined(__CUDA_ARCH_SPECIFIC__) && (__CUDA_ARCH_SPECIFIC__ >= 1000)) ||      \
    (defined(__CUDA_ARCH_FAMILY_SPECIFIC__) && (__CUDA_ARCH_FAMILY_SPECIFIC__ >= 1000))
#define TC_OK 1
#else
#define TC_OK 0
#endif

// ---------------- scratch (device globals) ----------------
__device__ __half g_xh[(size_t)M_DIM * C_DIM];
__device__ __half g_wlinT[NPAD * C_DIM];
__device__ __half g_fc1wT[(size_t)F_DIM * C_DIM];
__device__ __half g_fc2wT[(size_t)C_DIM * F_DIM];
__device__ float  g_wraw[(size_t)M_DIM * NPAD];
__device__ float  g_y[(size_t)M_DIM * C_DIM];
__device__ __half g_yh[(size_t)M_DIM * C_DIM];
__device__ __half g_h[(size_t)M_DIM * F_DIM];

// ---------------- helpers ----------------
__device__ __forceinline__ uint32_t smem_u32(const void* p) {
    uint32_t a;
    asm("{ .reg .u64 t; cvta.to.shared.u64 t, %1; cvt.u32.u64 %0, t; }" : "=r"(a) : "l"(p));
    return a;
}
__device__ __forceinline__ uint32_t elect_one() {
    uint32_t p;
    asm volatile("{ .reg .pred p; elect.sync _|p, 0xFFFFFFFF; selp.b32 %0, 1, 0, p; }" : "=r"(p));
    return p;
}
__device__ __forceinline__ void mbar_init(uint32_t a, uint32_t cnt) {
    asm volatile("mbarrier.init.shared.b64 [%0], %1;" :: "r"(a), "r"(cnt) : "memory");
}
__device__ __forceinline__ void mbar_expect_tx(uint32_t a, uint32_t bytes) {
    asm volatile("mbarrier.arrive.expect_tx.shared.b64 _, [%0], %1;" :: "r"(a), "r"(bytes) : "memory");
}
__device__ __forceinline__ void mbar_wait(uint32_t a, uint32_t parity) {
    uint32_t done;
    asm volatile(
        "{ .reg .pred p;\n\t"
        "mbarrier.try_wait.parity.acquire.cta.shared::cta.b64 p, [%1], %2;\n\t"
        "selp.b32 %0, 1, 0, p; }" : "=r"(done) : "r"(a), "r"(parity) : "memory");
    if (!done) {
        asm volatile(
            "{ .reg .pred P1;\n\t"
            "WL_%=:\n\t"
            "mbarrier.try_wait.parity.acquire.cta.shared::cta.b64 P1, [%0], %1, 0x989680;\n\t"
            "@P1 bra.uni WD_%=;\n\t"
            "bra.uni WL_%=;\n\t"
            "WD_%=: }" :: "r"(a), "r"(parity) : "memory");
    }
}
#if TC_OK
__device__ __forceinline__ uint32_t cluster_rank() {
    uint32_t r;
    asm("mov.u32 %0, %%cluster_ctarank;" : "=r"(r));
    return r;
}
__device__ __forceinline__ void mbar_arrive_cluster(uint32_t local_addr, uint32_t target_rank) {
    asm volatile(
        "{ .reg .b32 ra;\n\t"
        "mapa.shared::cluster.u32 ra, %0, %1;\n\t"
        "mbarrier.arrive.shared::cluster.b64 _, [ra]; }"
        :: "r"(local_addr), "r"(target_rank) : "memory");
}
#define CLUSTER_SYNC() do { \
    asm volatile("barrier.cluster.arrive.aligned;" ::: "memory"); \
    asm volatile("barrier.cluster.wait.aligned;" ::: "memory");   \
} while (0)

__device__ __forceinline__ void tma_2d(uint32_t dst, const void* map, int cx, int cy, uint32_t mbar) {
    asm volatile(
        "cp.async.bulk.tensor.2d.shared::cta.global.tile.mbarrier::complete_tx::bytes "
        "[%0], [%1, {%2, %3}], [%4];"
        :: "r"(dst), "l"(map), "r"(cx), "r"(cy), "r"(mbar) : "memory");
}
__device__ __forceinline__ void tma_3d_cg2(uint32_t dst, const void* map, int cx, int cy,
                                           uint32_t mbar) {
    asm volatile(
        "{\n\t"
        ".reg .b32 leaderBar;\n\t"
        "and.b32 leaderBar, %4, 0xFEFFFFFF;\n\t"
        "cp.async.bulk.tensor.3d.cta_group::2.shared::cluster.global"
        ".tile.mbarrier::complete_tx::bytes "
        "[%0], [%1, {%2, %3, %5}], [leaderBar];\n\t"
        "}"
        :: "r"(dst), "l"(map), "r"(cx), "r"(cy), "r"(mbar), "r"(0) : "memory");
}
__device__ __forceinline__ void mma_f16_ss(uint32_t d, uint64_t adesc, uint64_t bdesc,
                                           uint32_t idesc, uint32_t en) {
    asm volatile(
        "{ .reg .pred p;\n\t"
        "setp.ne.u32 p, %4, 0;\n\t"
        "tcgen05.mma.cta_group::1.kind::f16 [%0], %1, %2, %3, p; }"
        :: "r"(d), "l"(adesc), "l"(bdesc), "r"(idesc), "r"(en) : "memory");
}
__device__ __forceinline__ void mma_f16_ss_cg2(uint32_t d, uint64_t adesc, uint64_t bdesc,
                                               uint32_t idesc, uint32_t en) {
    asm volatile(
        "{ .reg .pred p;\n\t"
        "setp.ne.u32 p, %5, 0;\n\t"
        "tcgen05.mma.cta_group::2.kind::f16 [%0], %1, %2, %3, "
        "{%4, %4, %4, %4, %4, %4, %4, %4}, p; }"
        :: "r"(d), "l"(adesc), "l"(bdesc), "r"(idesc), "r"(0u), "r"(en) : "memory");
}
__device__ __forceinline__ void tc_commit(uint32_t mbar) {
    asm volatile(
        "tcgen05.commit.cta_group::1.mbarrier::arrive::one.shared::cluster.b64 [%0];"
        :: "r"(mbar) : "memory");
}
__device__ __forceinline__ void tc_commit_mc_cg2(uint32_t mbar, uint16_t mask) {
    asm volatile(
        "tcgen05.commit.cta_group::2.mbarrier::arrive::one.shared::cluster.multicast::cluster.b64 "
        "[%0], %1;"
        :: "r"(mbar), "h"(mask) : "memory");
}
#define TC_ALLOC(smem_addr, ncols) \
    asm volatile("tcgen05.alloc.cta_group::1.sync.aligned.shared::cta.b32 [%0], %1;" \
                 :: "r"(smem_addr), "r"(ncols) : "memory")
#define TC_RELINQ() \
    asm volatile("tcgen05.relinquish_alloc_permit.cta_group::1.sync.aligned;")
#define TC_DEALLOC(tmem, ncols) \
    asm volatile("tcgen05.dealloc.cta_group::1.sync.aligned.b32 %0, %1;" :: "r"(tmem), "r"(ncols))
#define TC_ALLOC_CG2(smem_addr, ncols) \
    asm volatile("tcgen05.alloc.cta_group::2.sync.aligned.shared::cta.b32 [%0], %1;" \
                 :: "r"(smem_addr), "r"(ncols) : "memory")
#define TC_RELINQ_CG2() \
    asm volatile("tcgen05.relinquish_alloc_permit.cta_group::2.sync.aligned;")
#define TC_DEALLOC_CG2(tmem, ncols) \
    asm volatile("tcgen05.dealloc.cta_group::2.sync.aligned.b32 %0, %1;" :: "r"(tmem), "r"(ncols))
#define TC_FENCE_AFTER()  asm volatile("tcgen05.fence::after_thread_sync;" ::: "memory")
#define TC_WAIT_LD()      asm volatile("tcgen05.wait::ld.sync.aligned;" ::: "memory")
#define TC_LD_X32(r, addr) \
    asm volatile("tcgen05.ld.sync.aligned.32x32b.x32.b32 " \
        "{%0, %1, %2, %3, %4, %5, %6, %7, %8, %9, %10, %11, %12, %13, %14, %15, " \
        " %16, %17, %18, %19, %20, %21, %22, %23, %24, %25, %26, %27, %28, %29, %30, %31}, [%32];" \
        : "=r"((r)[0]), "=r"((r)[1]), "=r"((r)[2]), "=r"((r)[3]), \
          "=r"((r)[4]), "=r"((r)[5]), "=r"((r)[6]), "=r"((r)[7]), \
          "=r"((r)[8]), "=r"((r)[9]), "=r"((r)[10]), "=r"((r)[11]), \
          "=r"((r)[12]), "=r"((r)[13]), "=r"((r)[14]), "=r"((r)[15]), \
          "=r"((r)[16]), "=r"((r)[17]), "=r"((r)[18]), "=r"((r)[19]), \
          "=r"((r)[20]), "=r"((r)[21]), "=r"((r)[22]), "=r"((r)[23]), \
          "=r"((r)[24]), "=r"((r)[25]), "=r"((r)[26]), "=r"((r)[27]), \
          "=r"((r)[28]), "=r"((r)[29]), "=r"((r)[30]), "=r"((r)[31]) \
        : "r"(addr))

__device__ __forceinline__ uint64_t smem_desc_sw128(uint32_t addr) {
    return ((uint64_t)2 << 61) | ((uint64_t)1 << 46) | ((uint64_t)64 << 32) |
           ((uint64_t)1 << 16) | (((uint64_t)addr >> 4) & 0x3FFF);
}
__device__ __forceinline__ constexpr uint32_t idesc_f16(int bn, int m) {
    return (1u << 4) | ((uint32_t)(bn / 8) << 17) | ((uint32_t)(m / 16) << 24);
}
#endif  // TC_OK

#if TC_OK
template <int EPI>
__device__ __forceinline__ void epi_write_chunk(const uint32_t* r, int row, int colbase,
                                                const float* __restrict__ bias,
                                                const float* __restrict__ res,
                                                void* __restrict__ Cv, int N) {
    if (EPI == 1) {
        __half* Ch = (__half*)Cv;
        __half2* dst = reinterpret_cast<__half2*>(&Ch[(size_t)row * N + colbase]);
        #pragma unroll
        for (int j = 0; j < 32; j += 2) {
            float v0 = fmaxf(__uint_as_float(r[j + 0]) + bias[colbase + j + 0], 0.f);
            float v1 = fmaxf(__uint_as_float(r[j + 1]) + bias[colbase + j + 1], 0.f);
            dst[j / 2] = __floats2half2_rn(v0, v1);
        }
    } else {
        float* C = (float*)Cv;
        float4* dst = reinterpret_cast<float4*>(&C[(size_t)row * N + colbase]);
        #pragma unroll
        for (int j = 0; j < 32; j += 4) {
            float4 v;
            v.x = __uint_as_float(r[j + 0]);
            v.y = __uint_as_float(r[j + 1]);
            v.z = __uint_as_float(r[j + 2]);
            v.w = __uint_as_float(r[j + 3]);
            if (EPI == 2) {
                v.x += bias[colbase + j + 0]; v.y += bias[colbase + j + 1];
                v.z += bias[colbase + j + 2]; v.w += bias[colbase + j + 3];
                float4 rv = *reinterpret_cast<const float4*>(&res[(size_t)row * N + colbase + j]);
                v.x += rv.x; v.y += rv.y; v.z += rv.z; v.w += rv.w;
            }
            dst[j / 4] = v;
        }
    }
}
#endif

// ================= plain warp-specialized tcgen05 fp16 GEMM (GEMM1) =================
template <int EPI, int BN_, int STG>
__global__ __launch_bounds__(256)
void tc_gemm_plain(const __grid_constant__ CUtensorMap tmA,
                   const __grid_constant__ CUtensorMap tmB,
                   const float* __restrict__ bias, const float* __restrict__ res,
                   void* __restrict__ C, int N, int NC) {
#if TC_OK
    constexpr int CA = 128 * 128;
    constexpr int CB = BN_ * 128;
    constexpr int CBYTES = CA + CB;
    constexpr int TCOLS = BN_;

    extern __shared__ __align__(1024) char smem[];
    const int tid  = threadIdx.x;
    const int warp = tid >> 5;
    const int lane = tid & 31;

    uint32_t sb = (smem_u32(smem) + 1023u) & ~1023u;
    const uint32_t tmem_ptr_addr = sb;
    const uint32_t mb_all = sb + 8 + 16 * STG;
    uint32_t mb_full[STG], mb_done[STG], bufA[STG], bufB[STG];
    #pragma unroll
    for (int s = 0; s < STG; s++) {
        mb_full[s] = sb + 8 + 8 * s;
        mb_done[s] = sb + 8 + 8 * STG + 8 * s;
        bufA[s] = sb + 1024 + s * CBYTES;
        bufB[s] = bufA[s] + CA;
    }

    if (warp == 0) { TC_ALLOC(tmem_ptr_addr, TCOLS); TC_RELINQ(); }
    if (tid == 0) {
        #pragma unroll
        for (int s = 0; s < STG; s++) { mbar_init(mb_full[s], 1); mbar_init(mb_done[s], 1); }
        mbar_init(mb_all, 1);
    }
    __syncthreads();

    uint32_t tmem;
    asm volatile("ld.shared.b32 %0, [%1];" : "=r"(tmem) : "r"(tmem_ptr_addr));

    const int tile_m = blockIdx.y * 128;
    const int tile_n = blockIdx.x * BN_;

    if (warp == 1 && elect_one()) {
        uint32_t phd = 0;
        for (int j = 0; j < NC; j++) {
            const int s = j % STG;
            if (j >= STG) { mbar_wait(mb_done[s], (phd >> s) & 1); phd ^= 1u << s; }
            mbar_expect_tx(mb_full[s], CBYTES);
            tma_2d(bufA[s], &tmA, j * KE, tile_m, mb_full[s]);
            tma_2d(bufB[s], &tmB, j * KE, tile_n, mb_full[s]);
        }
    }
    if (warp == 0 && elect_one()) {
        uint64_t ad[STG], bd[STG];
        #pragma unroll
        for (int s = 0; s < STG; s++) {
            ad[s] = smem_desc_sw128(bufA[s]);
            bd[s] = smem_desc_sw128(bufB[s]);
        }
        uint32_t phf = 0;
        for (int kc = 0; kc < NC; kc++) {
            const int s = kc % STG;
            mbar_wait(mb_full[s], (phf >> s) & 1); phf ^= 1u << s;
            #pragma unroll
            for (int s2 = 0; s2 < 4; s2++) {
                const uint32_t en = (kc > 0 || s2 > 0) ? 1u : 0u;
                mma_f16_ss(tmem, ad[s] + 2 * s2, bd[s] + 2 * s2, idesc_f16(BN_, 128), en);
            }
            tc_commit(mb_done[s]);
        }
        tc_commit(mb_all);
        mbar_wait(mb_all, 0);
    }
    __syncthreads();
    TC_FENCE_AFTER();
    {
        const int half_ = warp >> 2;
        const uint32_t dbase = tmem + half_ * (BN_ / 2);
        const int row = tile_m + (warp & 3) * 32 + lane;
        const int col0 = tile_n + half_ * (BN_ / 2);
        #pragma unroll 1
        for (int cc = 0; cc < BN_ / 64; cc++) {
            uint32_t r[32];
            TC_LD_X32(r, dbase + cc * 32);
            TC_WAIT_LD();
            epi_write_chunk<EPI>(r, row, col0 + cc * 32, bias, res, C, N);
        }
    }
    __syncthreads();
    if (warp == 0) TC_DEALLOC(tmem, TCOLS);
#endif
}

// ========== persistent cg2 512x256 (single TMEM buffer) — used for fc2 ==========
template <int EPI>
__global__ __launch_bounds__(320) __cluster_dims__(2, 1, 1)
void tc_gemm_cg2p(const __grid_constant__ CUtensorMap tmA,
                  const __grid_constant__ CUtensorMap tmB,
                  const float* __restrict__ bias, const float* __restrict__ res,
                  void* __restrict__ C, int N, int NC, int ntiles, int ntilesN) {
#if TC_OK
    constexpr int STG = 4;
    constexpr int CA = 2 * 128 * 128;
    constexpr int CB = 128 * 128;
    constexpr int CBYTES = CA + CB;
    constexpr int PAIR_BYTES = 2 * CBYTES;
    constexpr int TCOLS = 512;

    extern __shared__ __align__(1024) char smem[];
    const int tid  = threadIdx.x;
    const int warp = tid >> 5;
    const int lane = tid & 31;

    uint32_t sb = (smem_u32(smem) + 1023u) & ~1023u;
    const uint32_t tmem_ptr_addr = sb;
    uint32_t mb_full[STG], mb_done[STG], bufA[STG], bufB[STG];
    #pragma unroll
    for (int s = 0; s < STG; s++) {
        mb_full[s] = sb + 8 + 8 * s;
        mb_done[s] = sb + 8 + 8 * STG + 8 * s;
        bufA[s] = sb + 1024 + s * CBYTES;
        bufB[s] = bufA[s] + CA;
    }
    const uint32_t mb_tdone = sb + 8 + 16 * STG;
    const uint32_t mb_efree = sb + 16 + 16 * STG;

    if (warp == 0) { TC_ALLOC_CG2(tmem_ptr_addr, TCOLS); TC_RELINQ_CG2(); }
    if (tid == 0) {
        #pragma unroll
        for (int s = 0; s < STG; s++) { mbar_init(mb_full[s], 1); mbar_init(mb_done[s], 1); }
        mbar_init(mb_tdone, 1);
        mbar_init(mb_efree, 2);
    }
    __syncthreads();
    CLUSTER_SYNC();

    uint32_t tmem;
    asm volatile("ld.shared.b32 %0, [%1];" : "=r"(tmem) : "r"(tmem_ptr_addr));

    const int rank   = (int)cluster_rank();
    const int pair   = (int)(blockIdx.x >> 1);
    const int npairs = (int)(gridDim.x >> 1);

    if (warp == 8 && elect_one()) {
        uint32_t phd = 0;
        int gchunk = 0;
        for (int t = pair; t < ntiles; t += npairs) {
            const int tile_m = (t / ntilesN) * 512;
            const int tile_n = (t % ntilesN) * 256;
            const int rowA0 = tile_m + rank * 128;
            const int rowA1 = tile_m + 256 + rank * 128;
            const int rowB  = tile_n + rank * 128;
            for (int j = 0; j < NC; j++) {
                const int s = gchunk & (STG - 1);
                if (gchunk >= STG) { mbar_wait(mb_done[s], (phd >> s) & 1); phd ^= 1u << s; }
                if (rank == 0) mbar_expect_tx(mb_full[s], PAIR_BYTES);
                tma_3d_cg2(bufA[s],         &tmA, j * KE, rowA0, mb_full[s]);
                tma_3d_cg2(bufA[s] + 16384, &tmA, j * KE, rowA1, mb_full[s]);
                tma_3d_cg2(bufB[s],         &tmB, j * KE, rowB,  mb_full[s]);
                gchunk++;
            }
        }
    }
    if (rank == 0 && warp == 9 && elect_one()) {
        uint64_t adLo[STG], adHi[STG], bd[STG];
        #pragma unroll
        for (int s = 0; s < STG; s++) {
            adLo[s] = smem_desc_sw128(bufA[s]);
            adHi[s] = smem_desc_sw128(bufA[s] + 16384);
            bd[s]   = smem_desc_sw128(bufB[s]);
        }
        uint32_t phf = 0;
        int gchunk = 0, tilecnt = 0;
        for (int t = pair; t < ntiles; t += npairs) {
            if (tilecnt > 0) {
                mbar_wait(mb_efree, (tilecnt - 1) & 1);
                TC_FENCE_AFTER();
            }
            for (int j = 0; j < NC; j++) {
                const int s = gchunk & (STG - 1);
                mbar_wait(mb_full[s], (phf >> s) & 1); phf ^= 1u << s;
                #pragma unroll
                for (int s2 = 0; s2 < 4; s2++) {
                    const uint32_t en = (j > 0 || s2 > 0) ? 1u : 0u;
                    mma_f16_ss_cg2(tmem,       adLo[s] + 2 * s2, bd[s] + 2 * s2,
                                   idesc_f16(256, 256), en);
                    mma_f16_ss_cg2(tmem + 256, adHi[s] + 2 * s2, bd[s] + 2 * s2,
                                   idesc_f16(256, 256), en);
                }
                tc_commit_mc_cg2(mb_done[s], 0x3);
                gchunk++;
            }
            tc_commit_mc_cg2(mb_tdone, 0x3);
            tilecnt++;
        }
    }
    if (warp < 8) {
        int tilecnt = 0;
        for (int t = pair; t < ntiles; t += npairs) {
            const int tile_m = (t / ntilesN) * 512;
            const int tile_n = (t % ntilesN) * 256;
            mbar_wait(mb_tdone, tilecnt & 1);
            TC_FENCE_AFTER();
            const int half_ = warp >> 2;
            const uint32_t dbase = tmem + half_ * 256;
            const int row = tile_m + half_ * 256 + rank * 128 + (warp & 3) * 32 + lane;
            #pragma unroll 1
            for (int cc = 0; cc < 8; cc++) {
                uint32_t r[32];
                TC_LD_X32(r, dbase + cc * 32);
                TC_WAIT_LD();
                epi_write_chunk<EPI>(r, row, tile_n + cc * 32, bias, res, C, N);
            }
            asm volatile("bar.sync 10, 256;" ::: "memory");
            if (tid == 0) mbar_arrive_cluster(mb_efree, 0);
            tilecnt++;
        }
    }
    __syncthreads();
    if (warp == 0) TC_DEALLOC_CG2(tmem, TCOLS);
    CLUSTER_SYNC();
#endif
}

// ========== persistent cg2 256x256 with TMEM DOUBLE BUFFERING — used for fc1 ==========
// Tile i accumulates into TMEM half i&1 while epilogue drains half (i-1)&1:
// the MMA/TMA pipeline never stalls on the epilogue. 6-stage ring (32KB/CTA each).
template <int EPI>
__global__ __launch_bounds__(320) __cluster_dims__(2, 1, 1)
void tc_gemm_cg2db(const __grid_constant__ CUtensorMap tmA,
                   const __grid_constant__ CUtensorMap tmB,
                   const float* __restrict__ bias, const float* __restrict__ res,
                   void* __restrict__ C, int N, int NC, int ntiles, int ntilesN) {
#if TC_OK
    constexpr int STG = 6;
    constexpr int CA = 128 * 128;              // 16 KB A (128 rows)
    constexpr int CB = 128 * 128;              // 16 KB B (128 rows)
    constexpr int CBYTES = CA + CB;            // 32 KB per CTA per stage
    constexpr int PAIR_BYTES = 2 * CBYTES;     // 64 KB
    constexpr int TCOLS = 512;                 // two 256-col halves

    extern __shared__ __align__(1024) char smem[];
    const int tid  = threadIdx.x;
    const int warp = tid >> 5;
    const int lane = tid & 31;

    uint32_t sb = (smem_u32(smem) + 1023u) & ~1023u;
    const uint32_t tmem_ptr_addr = sb;
    uint32_t mb_full[STG], mb_done[STG], bufA[STG], bufB[STG];
    #pragma unroll
    for (int s = 0; s < STG; s++) {
        mb_full[s] = sb + 8 + 8 * s;
        mb_done[s] = sb + 8 + 8 * STG + 8 * s;
        bufA[s] = sb + 1024 + s * CBYTES;
        bufB[s] = bufA[s] + CA;
    }
    const uint32_t mb_tdone0 = sb + 8 + 16 * STG;
    const uint32_t mb_tdone1 = mb_tdone0 + 8;
    const uint32_t mb_efree0 = mb_tdone1 + 8;
    const uint32_t mb_efree1 = mb_efree0 + 8;

    if (warp == 0) { TC_ALLOC_CG2(tmem_ptr_addr, TCOLS); TC_RELINQ_CG2(); }
    if (tid == 0) {
        #pragma unroll
        for (int s = 0; s < STG; s++) { mbar_init(mb_full[s], 1); mbar_init(mb_done[s], 1); }
        mbar_init(mb_tdone0, 1); mbar_init(mb_tdone1, 1);
        mbar_init(mb_efree0, 2); mbar_init(mb_efree1, 2);
    }
    __syncthreads();
    CLUSTER_SYNC();

    uint32_t tmem;
    asm volatile("ld.shared.b32 %0, [%1];" : "=r"(tmem) : "r"(tmem_ptr_addr));

    const int rank   = (int)cluster_rank();
    const int pair   = (int)(blockIdx.x >> 1);
    const int npairs = (int)(gridDim.x >> 1);

    // ---------------- producer (warp 8, both CTAs) ----------------
    if (warp == 8 && elect_one()) {
        uint32_t phd = 0;
        int gchunk = 0, s = 0;
        for (int t = pair; t < ntiles; t += npairs) {
            const int rowA = (t / ntilesN) * 256 + rank * 128;
            const int rowB = (t % ntilesN) * 256 + rank * 128;
            for (int j = 0; j < NC; j++) {
                if (gchunk >= STG) { mbar_wait(mb_done[s], (phd >> s) & 1); phd ^= 1u << s; }
                if (rank == 0) mbar_expect_tx(mb_full[s], PAIR_BYTES);
                tma_3d_cg2(bufA[s], &tmA, j * KE, rowA, mb_full[s]);
                tma_3d_cg2(bufB[s], &tmB, j * KE, rowB, mb_full[s]);
                gchunk++;
                if (++s == STG) s = 0;
            }
        }
    }
    // ---------------- consumer (warp 9, leader only) ----------------
    if (rank == 0 && warp == 9 && elect_one()) {
        uint64_t ad[STG], bd[STG];
        #pragma unroll
        for (int s2 = 0; s2 < STG; s2++) {
            ad[s2] = smem_desc_sw128(bufA[s2]);
            bd[s2] = smem_desc_sw128(bufB[s2]);
        }
        uint32_t phf = 0;
        int s = 0, tilecnt = 0;
        int use0 = 0, use1 = 0;       // per-half use counters
        for (int t = pair; t < ntiles; t += npairs) {
            const int h = tilecnt & 1;
            const uint32_t dtm = tmem + h * 256;
            const int u = h ? use1 : use0;
            if (u >= 1) {                   // wait epilogue freed this half
                mbar_wait(h ? mb_efree1 : mb_efree0, (u - 1) & 1);
                TC_FENCE_AFTER();
            }
            for (int j = 0; j < NC; j++) {
                mbar_wait(mb_full[s], (phf >> s) & 1); phf ^= 1u << s;
                #pragma unroll
                for (int s2 = 0; s2 < 4; s2++) {
                    const uint32_t en = (j > 0 || s2 > 0) ? 1u : 0u;
                    mma_f16_ss_cg2(dtm, ad[s] + 2 * s2, bd[s] + 2 * s2,
                                   idesc_f16(256, 256), en);
                }
                tc_commit_mc_cg2(mb_done[s], 0x3);
                if (++s == STG) s = 0;
            }
            tc_commit_mc_cg2(h ? mb_tdone1 : mb_tdone0, 0x3);
            if (h) use1++; else use0++;
            tilecnt++;
        }
    }
    // ---------------- epilogue (warps 0-7, both CTAs) ----------------
    if (warp < 8) {
        int tilecnt = 0;
        int use0 = 0, use1 = 0;
        for (int t = pair; t < ntiles; t += npairs) {
            const int h = tilecnt & 1;
            const int u = h ? use1 : use0;
            const int tile_m = (t / ntilesN) * 256;
            const int tile_n = (t % ntilesN) * 256;
            mbar_wait(h ? mb_tdone1 : mb_tdone0, u & 1);
            TC_FENCE_AFTER();
            // 8 warps over 128 rows x 256 cols: colhalf = warp>>2 (128 cols), 4 warps / 128 rows
            const int colhalf = warp >> 2;
            const uint32_t dbase = tmem + h * 256 + colhalf * 128;
            const int row = tile_m + rank * 128 + (warp & 3) * 32 + lane;
            const int col0 = tile_n + colhalf * 128;
            #pragma unroll 1
            for (int cc = 0; cc < 4; cc++) {
                uint32_t r[32];
                TC_LD_X32(r, dbase + cc * 32);
                TC_WAIT_LD();
                epi_write_chunk<EPI>(r, row, col0 + cc * 32, bias, res, C, N);
            }
            asm volatile("bar.sync 10, 256;" ::: "memory");
            if (tid == 0) mbar_arrive_cluster(h ? mb_efree1 : mb_efree0, 0);
            if (h) use1++; else use0++;
            tilecnt++;
        }
    }
    __syncthreads();
    if (warp == 0) TC_DEALLOC_CG2(tmem, TCOLS);
    CLUSTER_SYNC();
#endif
}

// ================= fused prep: x->fp16 + all three fp16 transposes =================
#define F2H_BLOCKS 16384
#define TW_BLOCKS  128
#define T1_BLOCKS  2048
#define T2_BLOCKS  2048
#define PREP_BLOCKS (F2H_BLOCKS + TW_BLOCKS + T1_BLOCKS + T2_BLOCKS)

__global__ void prep_kernel(const float* __restrict__ x, __half* __restrict__ xh,
                            const float* __restrict__ w_lin, __half* __restrict__ wlinT,
                            const float* __restrict__ fc1_w, __half* __restrict__ fc1wT,
                            const float* __restrict__ fc2_w, __half* __restrict__ fc2wT) {
    __shared__ float tile[64][33];
    const int tx = threadIdx.x, ty = threadIdx.y;
    int bid = blockIdx.x;

    if (bid < F2H_BLOCKS) {
        const int i = bid * 256 + ty * 32 + tx;
        float2 v = reinterpret_cast<const float2*>(x)[i];
        reinterpret_cast<__half2*>(xh)[i] = __floats2half2_rn(v.x, v.y);
        return;
    }
    bid -= F2H_BLOCKS;

    const float* in; __half* out;
    int R, Cc, Cp, gx;
    if (bid < TW_BLOCKS) {
        in = w_lin; out = wlinT; R = C_DIM; Cc = H_DIM * K_TAPS; Cp = NPAD; gx = NPAD / 32;
    } else if (bid < TW_BLOCKS + T1_BLOCKS) {
        bid -= TW_BLOCKS;
        in = fc1_w; out = fc1wT; R = C_DIM; Cc = F_DIM; Cp = F_DIM; gx = F_DIM / 32;
    } else {
        bid -= TW_BLOCKS + T1_BLOCKS;
        in = fc2_w; out = fc2wT; R = F_DIM; Cc = C_DIM; Cp = C_DIM; gx = C_DIM / 32;
    }
    const int c0 = (bid % gx) * 32;
    const int r0 = (bid / gx) * 64;

    #pragma unroll
    for (int i = 0; i < 64; i += 8) {
        const int y = r0 + ty + i;
        const int xq = c0 + tx;
        float v = 0.f;
        if (xq < Cc && y < R) v = in[(size_t)y * Cc + xq];
        tile[ty + i][tx] = v;
    }
    __syncthreads();
    #pragma unroll
    for (int i = 0; i < 32; i += 8) {
        const int oy = c0 + ty + i;
        const int ox = r0 + 2 * tx;
        if (oy < Cp) {
            __half2 v = __floats2half2_rn(tile[2 * tx][ty + i], tile[2 * tx + 1][ty + i]);
            *reinterpret_cast<__half2*>(&out[(size_t)oy * R + ox]) = v;
        }
    }
}

// ================= warp-per-timestep softmax + causal conv + LayerNorm =================
__global__ __launch_bounds__(512, 2)
void dynconv_ln_kernel(const __half* __restrict__ xh, const float* __restrict__ wraw,
                       const float* __restrict__ b_lin,
                       const float* __restrict__ ln_g, const float* __restrict__ ln_b,
                       float* __restrict__ y, __half* __restrict__ yh) {
    extern __shared__ char smc[];
    __half2* xs2 = reinterpret_cast<__half2*>(smc);
    float*   ws  = reinterpret_cast<float*>(smc + DC_WS_OFF);
    float*   g_s = reinterpret_cast<float*>(smc + DC_G_OFF);
    float*   b_s = reinterpret_cast<float*>(smc + DC_B_OFF);

    const int t0  = blockIdx.x * TT;
    const int b   = blockIdx.y;
    const int tid = threadIdx.x;

    {
        uint4* dst = reinterpret_cast<uint4*>(smc);
        const int total = XS_ROWS * (C_DIM / 8);
        for (int i = tid; i < total; i += 512) {
            const int r = i / (C_DIM / 8);
            const int cc = i % (C_DIM / 8);
            const int t = t0 - HALO + r;
            uint4 v = make_uint4(0u, 0u, 0u, 0u);
            if (t >= 0)
                v = reinterpret_cast<const uint4*>(&xh[((size_t)(t * B_DIM + b)) * C_DIM])[cc];
            dst[i] = v;
        }
    }
    for (int i = tid; i < TT * (H_DIM * K_TAPS); i += 512) {
        const int lt = i / (H_DIM * K_TAPS);
        const int j  = i % (H_DIM * K_TAPS);
        ws[i] = wraw[(size_t)((t0 + lt) * B_DIM + b) * NPAD + j] + b_lin[j];
    }
    for (int i = tid; i < C_DIM; i += 512) { g_s[i] = ln_g[i]; b_s[i] = ln_b[i]; }
    __syncthreads();

    if (tid < TT * H_DIM) {
        const int lt = tid >> 4;
        const int hd = tid & 15;
        float* p = ws + lt * (H_DIM * K_TAPS) + hd * K_TAPS;
        float mx = -1e30f;
        #pragma unroll
        for (int k = 0; k < K_TAPS; k++) mx = fmaxf(mx, p[k]);
        float e[K_TAPS]; float s = 0.f;
        #pragma unroll
        for (int k = 0; k < K_TAPS; k++) { e[k] = expf(p[k] - mx); s += e[k]; }
        const float inv = 1.0f / s;
        #pragma unroll
        for (int k = 0; k < K_TAPS; k++) p[k] = e[k] * inv;
    }
    __syncthreads();

    const int w    = tid >> 5;
    const int lane = tid & 31;
    const float* wrow = ws + w * (H_DIM * K_TAPS);

    __half2 ah[16];
    float s1 = 0.f, s2 = 0.f;
    #pragma unroll
    for (int j = 0; j < 16; j++) {
        float acc0 = 0.f, acc1 = 0.f;
        #pragma unroll
        for (int k = 0; k < K_TAPS; k++) {
            const float wgt = wrow[j * K_TAPS + k];
            const float2 xv = __half22float2(xs2[(w + k) * (C_DIM / 2) + lane + 32 * j]);
            acc0 += wgt * xv.x;
            acc1 += wgt * xv.y;
        }
        ah[j] = __floats2half2_rn(acc0, acc1);
        s1 += acc0 + acc1;
        s2 += acc0 * acc0 + acc1 * acc1;
    }
    #pragma unroll
    for (int off = 16; off > 0; off >>= 1) {
        s1 += __shfl_xor_sync(0xFFFFFFFFu, s1, off);
        s2 += __shfl_xor_sync(0xFFFFFFFFu, s2, off);
    }
    const float mu   = s1 * (1.0f / C_DIM);
    const float var  = s2 * (1.0f / C_DIM) - mu * mu;
    const float rstd = rsqrtf(var + LN_EPS);

    const size_t base = (size_t)((t0 + w) * B_DIM + b) * C_DIM;
    #pragma unroll
    for (int j = 0; j < 16; j++) {
        const int c = 2 * lane + 64 * j;
        const float2 a = __half22float2(ah[j]);
        const float v0 = (a.x - mu) * rstd * g_s[c]     + b_s[c];
        const float v1 = (a.y - mu) * rstd * g_s[c + 1] + b_s[c + 1];
        *reinterpret_cast<float2*>(&y[base + c])   = make_float2(v0, v1);
        *reinterpret_cast<__half2*>(&yh[base + c]) = __floats2half2_rn(v0, v1);
    }
}

// ================= host side =================
typedef CUresult (*PFN_encodeTiled)(CUtensorMap*, CUtensorMapDataType, cuuint32_t, void*,
                                    const cuuint64_t*, const cuuint64_t*, const cuuint32_t*,
                                    const cuuint32_t*, CUtensorMapInterleave, CUtensorMapSwizzle,
                                    CUtensorMapL2promotion, CUtensorMapFloatOOBfill);

static PFN_encodeTiled get_encoder() {
    static PFN_encodeTiled fn = nullptr;
    if (!fn) {
        void* h = dlopen("libcuda.so.1", RTLD_LAZY | RTLD_GLOBAL);
        if (!h) h = dlopen("libcuda.so", RTLD_LAZY | RTLD_GLOBAL);
        if (h) fn = (PFN_encodeTiled)dlsym(h, "cuTensorMapEncodeTiled");
    }
    return fn;
}

static void make_map_h2(CUtensorMap* m, const void* ptr, uint64_t d0, uint64_t d1, uint32_t b1) {
    cuuint64_t dims[2] = { d0, d1 };
    cuuint64_t strides[1] = { d0 * 2 };
    cuuint32_t box[2] = { KE, b1 };
    cuuint32_t es[2] = { 1, 1 };
    PFN_encodeTiled enc = get_encoder();
    if (enc)
        enc(m, CU_TENSOR_MAP_DATA_TYPE_FLOAT16, 2, (void*)ptr, dims, strides, box, es,
            CU_TENSOR_MAP_INTERLEAVE_NONE, CU_TENSOR_MAP_SWIZZLE_128B,
            CU_TENSOR_MAP_L2_PROMOTION_L2_128B, CU_TENSOR_MAP_FLOAT_OOB_FILL_NONE);
}
static void make_map_h3(CUtensorMap* m, const void* ptr, uint64_t d0, uint64_t d1) {
    cuuint64_t dims[3] = { d0, d1, 1 };
    cuuint64_t strides[2] = { d0 * 2, d0 * d1 * 2 };
    cuuint32_t box[3] = { KE, 128, 1 };
    cuuint32_t es[3] = { 1, 1, 1 };
    PFN_encodeTiled enc = get_encoder();
    if (enc)
        enc(m, CU_TENSOR_MAP_DATA_TYPE_FLOAT16, 3, (void*)ptr, dims, strides, box, es,
            CU_TENSOR_MAP_INTERLEAVE_NONE, CU_TENSOR_MAP_SWIZZLE_128B,
            CU_TENSOR_MAP_L2_PROMOTION_L2_128B, CU_TENSOR_MAP_FLOAT_OOB_FILL_NONE);
}

extern "C" void kernel_launch(void* const* d_in, const int* in_sizes, int n_in,
                              void* d_out, int out_size) {
    const float* x     = (const float*)d_in[0];
    const float* w_lin = (const float*)d_in[1];
    const float* b_lin = (const float*)d_in[2];
    const float* ln_g  = (const float*)d_in[3];
    const float* ln_b  = (const float*)d_in[4];
    const float* fc1_w = (const float*)d_in[5];
    const float* fc1_b = (const float*)d_in[6];
    const float* fc2_w = (const float*)d_in[7];
    const float* fc2_b = (const float*)d_in[8];
    float* out = (float*)d_out;

    __half *xh, *wlinT, *fc1wT, *fc2wT, *yh, *h;
    float *wraw, *y;
    cudaGetSymbolAddress((void**)&xh, g_xh);
    cudaGetSymbolAddress((void**)&wlinT, g_wlinT);
    cudaGetSymbolAddress((void**)&fc1wT, g_fc1wT);
    cudaGetSymbolAddress((void**)&fc2wT, g_fc2wT);
    cudaGetSymbolAddress((void**)&wraw, g_wraw);
    cudaGetSymbolAddress((void**)&y, g_y);
    cudaGetSymbolAddress((void**)&yh, g_yh);
    cudaGetSymbolAddress((void**)&h, g_h);

    const int smem_g1  = 1024 + 5 * (128 * 128 + 128 * 128);           // 161 KB
    const int smem_cg2 = 1024 + 4 * (2 * 128 * 128 + 128 * 128);       // 193 KB
    const int smem_db  = 1024 + 6 * (128 * 128 + 128 * 128);           // 193 KB
    cudaFuncSetAttribute((const void*)tc_gemm_plain<0, 128, 5>,
                         cudaFuncAttributeMaxDynamicSharedMemorySize, smem_g1);
    cudaFuncSetAttribute((const void*)tc_gemm_cg2db<1>,
                         cudaFuncAttributeMaxDynamicSharedMemorySize, smem_db);
    cudaFuncSetAttribute((const void*)tc_gemm_cg2p<2>,
                         cudaFuncAttributeMaxDynamicSharedMemorySize, smem_cg2);
    cudaFuncSetAttribute((const void*)dynconv_ln_kernel,
                         cudaFuncAttributeMaxDynamicSharedMemorySize, DC_SMEM);

    CUtensorMap mA1{}, mB1{}, mA2{}, mB2{}, mA3{}, mB3{};
    make_map_h2(&mA1, xh,    C_DIM, M_DIM, 128);
    make_map_h2(&mB1, wlinT, C_DIM, NPAD,  128);
    make_map_h3(&mA2, yh,    C_DIM, M_DIM);
    make_map_h3(&mB2, fc1wT, C_DIM, F_DIM);
    make_map_h3(&mA3, h,     F_DIM, M_DIM);
    make_map_h3(&mB3, fc2wT, F_DIM, C_DIM);

    // 1) fused prep
    prep_kernel<<<PREP_BLOCKS, dim3(32, 8)>>>(x, xh, w_lin, wlinT, fc1_w, fc1wT, fc2_w, fc2wT);
    // 2) conv-weight projection
    tc_gemm_plain<0, 128, 5><<<dim3(NPAD / 128, M_DIM / 128), 256, smem_g1>>>(
        mA1, mB1, nullptr, nullptr, wraw, NPAD, C_DIM / KE);
    // 3) softmax + conv + LN
    dynconv_ln_kernel<<<dim3(T_DIM / TT, B_DIM), 512, DC_SMEM>>>(
        xh, wraw, b_lin, ln_g, ln_b, y, yh);
    // 4) fc1 + ReLU -> fp16 h : persistent 256x256, TMEM double-buffered.
    //    512 tiles = (8192/256) m x (4096/256) n = 32 x 16.     <-- launch #4 = profiled
    tc_gemm_cg2db<1><<<148, 320, smem_db>>>(
        mA2, mB2, fc1_b, nullptr, h, F_DIM, C_DIM / KE, 512, 16);
    // 5) fc2 + bias + residual -> fp32 out : persistent 512x256 (at ingest floor)
    tc_gemm_cg2p<2><<<148, 320, smem_cg2>>>(
        mA3, mB3, fc2_b, y, out, C_DIM, F_DIM / KE, 64, 4);
}